// round 15
// baseline (speedup 1.0000x reference)
#include <cuda_runtime.h>
#include <cuda_fp16.h>
#include <math.h>

#define FDIM 256
#define BMAX 1024
#define MMAX 500000
#define NMAX 200000
#define CPW  32      // candidates per dot-warp (8 iterations x 4)
#define PREBLK 1024  // blocks doing per-node precompute inside k_fused

// Scratch (allocation-free: __device__ globals)
__device__ float    g_groot[BMAX * FDIM];   // per-root x_r * w_ego_root * w_ego_u
__device__ float2   g_rootsc[BMAX];         // {1/max(nr,eps), budgets/200}
__device__ float    g_sv[BMAX];             // x_r . w_layer_v
__device__ unsigned g_pnorm[BMAX];          // encoded float max
__device__ float    g_agg[MMAX];            // segment_sum(sv[edge_src] -> edge_dst)
__device__ float    g_dot[MMAX];            // raw dot(x_u, g_b)
__device__ float    g_pu[MMAX];             // p_u before normalization
__device__ float4   g_node[NMAX];           // {1/max(nu,eps), su, 0.5*n_imp, 0}
__device__ __half   g_xh[(size_t)NMAX * FDIM];  // fp16 cache of x (102MB, ~L2-resident)

__device__ __forceinline__ unsigned f2key(float f) {
    unsigned u = __float_as_uint(f);
    return (u & 0x80000000u) ? ~u : (u | 0x80000000u);
}
__device__ __forceinline__ float key2f(unsigned k) {
    unsigned u = (k & 0x80000000u) ? (k ^ 0x80000000u) : ~k;
    return __uint_as_float(u);
}
__device__ __forceinline__ float dot4(float4 a, float4 b) {
    return a.x * b.x + a.y * b.y + a.z * b.z + a.w * b.w;
}
__device__ __forceinline__ float sq4(float4 a, float4 w) {
    float t0 = a.x * w.x, t1 = a.y * w.y, t2 = a.z * w.z, t3 = a.w * w.w;
    return t0 * t0 + t1 * t1 + t2 * t2 + t3 * t3;
}
__device__ __forceinline__ uint2 f4_to_h4(float4 v) {
    __half2 h0 = __floats2half2_rn(v.x, v.y);
    __half2 h1 = __floats2half2_rn(v.z, v.w);
    uint2 r;
    r.x = *(unsigned*)&h0;
    r.y = *(unsigned*)&h1;
    return r;
}
// h = 8 halves (cols k..k+7); ga/gb the matching two float4 of g
__device__ __forceinline__ float dot_h8(uint4 h, float4 ga, float4 gb) {
    __half2 h0 = *(__half2*)&h.x;
    __half2 h1 = *(__half2*)&h.y;
    __half2 h2 = *(__half2*)&h.z;
    __half2 h3 = *(__half2*)&h.w;
    float2 f0 = __half22float2(h0);
    float2 f1 = __half22float2(h1);
    float2 f2 = __half22float2(h2);
    float2 f3 = __half22float2(h3);
    return f0.x*ga.x + f0.y*ga.y + f1.x*ga.z + f1.y*ga.w
         + f2.x*gb.x + f2.y*gb.y + f3.x*gb.z + f3.y*gb.w;
}

// K1: per-root precompute (one block per root) + zero g_agg (strided).
__global__ void k_root(const float* __restrict__ x,
                       const float* __restrict__ w_ego_root,
                       const float* __restrict__ w_ego_u,
                       const float* __restrict__ w_layer_v,
                       const float* __restrict__ budgets,
                       const int*   __restrict__ batch_nodes,
                       int B, int M)
{
    int b = blockIdx.x;
    int f = threadIdx.x;

    for (int j = b * FDIM + f; j < M; j += gridDim.x * FDIM) g_agg[j] = 0.0f;

    float xr = x[(size_t)batch_nodes[b] * FDIM + f];
    float h  = xr * w_ego_root[f];
    g_groot[b * FDIM + f] = h * w_ego_u[f];
    float s1 = h * h;
    float s2 = xr * w_layer_v[f];

    __shared__ float sh1[8], sh2[8];
    #pragma unroll
    for (int o = 16; o; o >>= 1) {
        s1 += __shfl_xor_sync(0xffffffffu, s1, o);
        s2 += __shfl_xor_sync(0xffffffffu, s2, o);
    }
    int w = f >> 5, l = f & 31;
    if (l == 0) { sh1[w] = s1; sh2[w] = s2; }
    __syncthreads();
    if (f == 0) {
        float t1 = 0.f, t2 = 0.f;
        #pragma unroll
        for (int i = 0; i < 8; i++) { t1 += sh1[i]; t2 += sh2[i]; }
        g_rootsc[b] = make_float2(1.0f / fmaxf(sqrtf(t1), 1e-6f),
                                  budgets[b] * (1.0f / 200.0f));
        g_sv[b] = t2;
        g_pnorm[b] = f2key(-INFINITY);
    }
}

// K2: per-node precompute + fp16 x-cache write (blocks [0, PREBLK))
//     fused with edge scatter-add (remaining blocks). Independent halves.
__global__ void __launch_bounds__(256)
k_fused(const float* __restrict__ x,
        const float* __restrict__ w_ego_u,
        const float* __restrict__ w_layer_u,
        const float* __restrict__ n_imp,
        const int* __restrict__ edge_src,
        const int* __restrict__ edge_dst,
        int N, int E)
{
    const float4* x4 = (const float4*)x;

    if (blockIdx.x < PREBLK) {
        int lane = threadIdx.x & 31;
        int gw = (blockIdx.x * blockDim.x + threadIdx.x) >> 5;
        int nw = PREBLK * 8;

        float4 wea = __ldg(((const float4*)w_ego_u)   + lane);
        float4 web = __ldg(((const float4*)w_ego_u)   + lane + 32);
        float4 wla = __ldg(((const float4*)w_layer_u) + lane);
        float4 wlb = __ldg(((const float4*)w_layer_u) + lane + 32);

        for (int n = gw * 2; n < N; n += nw * 2) {
            bool two = (n + 1 < N);
            float4 a0 = __ldg(x4 + (size_t)n * 64 + lane);
            float4 b0 = __ldg(x4 + (size_t)n * 64 + lane + 32);
            int n1 = two ? n + 1 : n;
            float4 a1 = __ldg(x4 + (size_t)n1 * 64 + lane);
            float4 b1 = __ldg(x4 + (size_t)n1 * 64 + lane + 32);

            // fp16 cache write: cols [4l,4l+4) and [128+4l,128+4l+4)
            uint2* xo0 = (uint2*)(g_xh + (size_t)n * FDIM);
            xo0[lane]      = f4_to_h4(a0);
            xo0[lane + 32] = f4_to_h4(b0);
            if (two) {
                uint2* xo1 = (uint2*)(g_xh + (size_t)n1 * FDIM);
                xo1[lane]      = f4_to_h4(a1);
                xo1[lane + 32] = f4_to_h4(b1);
            }

            float nu0 = sq4(a0, wea) + sq4(b0, web);
            float su0 = dot4(a0, wla) + dot4(b0, wlb);
            float nu1 = sq4(a1, wea) + sq4(b1, web);
            float su1 = dot4(a1, wla) + dot4(b1, wlb);

            nu0 += __shfl_xor_sync(0xffffffffu, nu0, 16);
            su0 += __shfl_xor_sync(0xffffffffu, su0, 16);
            nu1 += __shfl_xor_sync(0xffffffffu, nu1, 16);
            su1 += __shfl_xor_sync(0xffffffffu, su1, 16);
            bool hi16 = (lane & 16) != 0;
            float v0 = hi16 ? su0 : nu0;      // lanes<16: nu, >=16: su
            float v1 = hi16 ? su1 : nu1;
            #pragma unroll
            for (int o = 8; o; o >>= 1) {
                v0 += __shfl_xor_sync(0xffffffffu, v0, o);
                v1 += __shfl_xor_sync(0xffffffffu, v1, o);
            }
            float su0f = __shfl_sync(0xffffffffu, v0, 16);
            float su1f = __shfl_sync(0xffffffffu, v1, 16);
            if (lane == 0) {
                g_node[n] = make_float4(1.0f / fmaxf(sqrtf(v0), 1e-6f), su0f,
                                        0.5f * __ldg(n_imp + n), 0.0f);
                if (two)
                    g_node[n1] = make_float4(1.0f / fmaxf(sqrtf(v1), 1e-6f), su1f,
                                             0.5f * __ldg(n_imp + n1), 0.0f);
            }
        }
    } else {
        // ---- edge scatter-add: 4 edges per thread ----
        int i = ((blockIdx.x - PREBLK) * (int)blockDim.x + (int)threadIdx.x) * 4;
        if (i + 3 < E) {
            int4 s = *(const int4*)(edge_src + i);
            int4 d = *(const int4*)(edge_dst + i);
            atomicAdd(&g_agg[d.x], g_sv[s.x]);
            atomicAdd(&g_agg[d.y], g_sv[s.y]);
            atomicAdd(&g_agg[d.z], g_sv[s.z]);
            atomicAdd(&g_agg[d.w], g_sv[s.w]);
        } else {
            for (int j = i; j < E; j++)
                atomicAdd(&g_agg[edge_dst[j]], g_sv[edge_src[j]]);
        }
    }
}

// K3: candidate dots from the fp16 cache. 8-lanes-per-candidate, 4/warp-iter.
// Lane s covers cols [32s, 32s+32) = 4 uint4 loads (64B). g row in L1 (f32).
__global__ void __launch_bounds__(256)
k_dot(const int* __restrict__ u_ids,
      const int* __restrict__ batch_ptr, int M)
{
    int lane  = threadIdx.x & 31;
    int gwarp = blockIdx.x * 8 + (threadIdx.x >> 5);
    int c = lane >> 3;          // candidate slot 0..3
    int s = lane & 7;           // sublane 0..7
    const float4* g4 = (const float4*)g_groot;
    const uint4*  xh = (const uint4*)g_xh;   // 8 halves per uint4; row = 32 uint4

    int Mmain = M & ~3;

    // tail: grid-warp 0 handles [Mmain, M) with a 32-lane path
    if (gwarp == 0 && Mmain < M) {
        for (int m = Mmain; m < M; m++) {
            int u = __ldg(u_ids + m);
            int b = __ldg(batch_ptr + m);
            uint4 hv = __ldg(xh + (size_t)u * 32 + lane);     // cols [8l, 8l+8)
            const float4* gr = g4 + (size_t)b * 64 + lane * 2;
            float d = dot_h8(hv, __ldg(gr), __ldg(gr + 1));
            #pragma unroll
            for (int o = 16; o; o >>= 1)
                d += __shfl_xor_sync(0xffffffffu, d, o);
            if (lane == 0) g_dot[m] = d;
        }
    }

    int base = gwarp * CPW;
    if (base >= Mmain) return;
    int lim = base + CPW; if (lim > Mmain) lim = Mmain;

    for (int m0 = base; m0 < lim; m0 += 4) {
        int4 uu = *(const int4*)(u_ids + m0);
        int4 bb = *(const int4*)(batch_ptr + m0);
        int u = (c == 0) ? uu.x : (c == 1) ? uu.y : (c == 2) ? uu.z : uu.w;
        int b = (c == 0) ? bb.x : (c == 1) ? bb.y : (c == 2) ? bb.z : bb.w;

        // 4 independent 16B loads per lane (32 halves = cols [32s, 32s+32))
        const uint4* xr = xh + (size_t)u * 32 + s * 4;
        uint4 h0 = __ldg(xr);
        uint4 h1 = __ldg(xr + 1);
        uint4 h2 = __ldg(xr + 2);
        uint4 h3 = __ldg(xr + 3);

        const float4* gr = g4 + (size_t)b * 64 + s * 8;
        float dot = dot_h8(h0, __ldg(gr),     __ldg(gr + 1))
                  + dot_h8(h1, __ldg(gr + 2), __ldg(gr + 3))
                  + dot_h8(h2, __ldg(gr + 4), __ldg(gr + 5))
                  + dot_h8(h3, __ldg(gr + 6), __ldg(gr + 7));

        #pragma unroll
        for (int o = 4; o; o >>= 1)
            dot += __shfl_xor_sync(0xffffffffu, dot, o);

        if (s == 0) g_dot[m0 + c] = dot;   // 4 lanes, 16B coalesced
    }
}

// K4: finalize — p_u from dot/agg/node tables + per-batch max (warp-merged).
__global__ void __launch_bounds__(256)
k_fin1(const int* __restrict__ u_ids,
       const int* __restrict__ batch_ptr, int M)
{
    int idx = blockIdx.x * blockDim.x + threadIdx.x;
    int m = idx * 4;
    bool full = (m + 3 < M);
    unsigned act = __ballot_sync(0xffffffffu, full);

    if (full) {
        int4   uu = *(const int4*)(u_ids + m);
        int4   bb = *(const int4*)(batch_ptr + m);
        float4 dt = *(const float4*)(g_dot + m);
        float4 ag = *(const float4*)(g_agg + m);

        float4 nd0 = __ldg((const float4*)g_node + uu.x);
        float4 nd1 = __ldg((const float4*)g_node + uu.y);
        float4 nd2 = __ldg((const float4*)g_node + uu.z);
        float4 nd3 = __ldg((const float4*)g_node + uu.w);
        float2 rs0 = __ldg(g_rootsc + bb.x);
        float2 rs1 = __ldg(g_rootsc + bb.y);
        float2 rs2 = __ldg(g_rootsc + bb.z);
        float2 rs3 = __ldg(g_rootsc + bb.w);

        float4 r;
        r.x = (dt.x * rs0.x * nd0.x + tanhf(ag.x + nd0.y)) * nd0.z * rs0.y;
        r.y = (dt.y * rs1.x * nd1.x + tanhf(ag.y + nd1.y)) * nd1.z * rs1.y;
        r.z = (dt.z * rs2.x * nd2.x + tanhf(ag.z + nd2.y)) * nd2.z * rs2.y;
        r.w = (dt.w * rs3.x * nd3.x + tanhf(ag.w + nd3.y)) * nd3.z * rs3.y;
        *(float4*)(g_pu + m) = r;

        unsigned kx = f2key(r.x), ky = f2key(r.y);
        unsigned kz = f2key(r.z), kw = f2key(r.w);
        bool uni4 = (bb.x == bb.w);
        unsigned kmax = kx > ky ? kx : ky;
        kmax = kmax > kz ? kmax : kz;
        kmax = kmax > kw ? kmax : kw;

        if (act == 0xffffffffu) {     // whole warp in this path: safe to shfl
            unsigned bFirst = __shfl_sync(0xffffffffu, (unsigned)bb.x, 0);
            bool warpUni = __all_sync(0xffffffffu,
                                      uni4 && (unsigned)bb.x == bFirst);
            if (warpUni) {
                #pragma unroll
                for (int o = 16; o; o >>= 1) {
                    unsigned t = __shfl_xor_sync(0xffffffffu, kmax, o);
                    kmax = kmax > t ? kmax : t;
                }
                if ((threadIdx.x & 31) == 0) atomicMax(&g_pnorm[bb.x], kmax);
                return;
            }
        }
        if (uni4) {
            atomicMax(&g_pnorm[bb.x], kmax);
        } else {
            atomicMax(&g_pnorm[bb.x], kx);
            atomicMax(&g_pnorm[bb.y], ky);
            atomicMax(&g_pnorm[bb.z], kz);
            atomicMax(&g_pnorm[bb.w], kw);
        }
    } else {
        for (int j = m; j < M; j++) {
            int u = __ldg(u_ids + j);
            int b = __ldg(batch_ptr + j);
            float4 nd = __ldg((const float4*)g_node + u);
            float2 rs = __ldg(g_rootsc + b);
            float p = (g_dot[j] * rs.x * nd.x + tanhf(g_agg[j] + nd.y))
                      * nd.z * rs.y;
            g_pu[j] = p;
            atomicMax(&g_pnorm[b], f2key(p));
        }
    }
}

// K5: normalize + nan/inf replace + clip (vectorized)
__global__ void k_final(const int* __restrict__ batch_ptr,
                        float* __restrict__ out, int M)
{
    int m = (blockIdx.x * blockDim.x + threadIdx.x) * 4;
    if (m + 3 < M) {
        int4   bp = *(const int4*)(batch_ptr + m);
        float4 pu = *(const float4*)(g_pu + m);
        float4 r;
        {
            float p = pu.x / key2f(g_pnorm[bp.x]) + 1.0f;
            if (isnan(p)) p = 0.0f; else if (isinf(p)) p = 1.0f;
            r.x = fminf(fmaxf(p, 1e-5f), 1.0f);
        }
        {
            float p = pu.y / key2f(g_pnorm[bp.y]) + 1.0f;
            if (isnan(p)) p = 0.0f; else if (isinf(p)) p = 1.0f;
            r.y = fminf(fmaxf(p, 1e-5f), 1.0f);
        }
        {
            float p = pu.z / key2f(g_pnorm[bp.z]) + 1.0f;
            if (isnan(p)) p = 0.0f; else if (isinf(p)) p = 1.0f;
            r.z = fminf(fmaxf(p, 1e-5f), 1.0f);
        }
        {
            float p = pu.w / key2f(g_pnorm[bp.w]) + 1.0f;
            if (isnan(p)) p = 0.0f; else if (isinf(p)) p = 1.0f;
            r.w = fminf(fmaxf(p, 1e-5f), 1.0f);
        }
        *(float4*)(out + m) = r;
    } else {
        for (int j = m; j < M; j++) {
            float p = g_pu[j] / key2f(g_pnorm[batch_ptr[j]]) + 1.0f;
            if (isnan(p)) p = 0.0f; else if (isinf(p)) p = 1.0f;
            out[j] = fminf(fmaxf(p, 1e-5f), 1.0f);
        }
    }
}

extern "C" void kernel_launch(void* const* d_in, const int* in_sizes, int n_in,
                              void* d_out, int out_size)
{
    const float* x           = (const float*)d_in[0];
    const float* w_ego_root  = (const float*)d_in[1];
    const float* w_ego_u     = (const float*)d_in[2];
    const float* w_layer_v   = (const float*)d_in[3];
    const float* w_layer_u   = (const float*)d_in[4];
    const float* n_imp       = (const float*)d_in[5];
    const float* budgets     = (const float*)d_in[6];
    const int*   batch_nodes = (const int*)d_in[7];
    const int*   u_ids       = (const int*)d_in[8];
    const int*   batch_ptr   = (const int*)d_in[9];
    const int*   edge_src    = (const int*)d_in[10];
    const int*   edge_dst    = (const int*)d_in[11];
    float* out = (float*)d_out;

    int B = in_sizes[7];
    int M = in_sizes[8];
    int E = in_sizes[10];
    int N = in_sizes[0] / FDIM;

    k_root<<<B, FDIM>>>(x, w_ego_root, w_ego_u, w_layer_v, budgets,
                        batch_nodes, B, M);

    int edgeBlocks = (E / 4 + 255) / 256;
    k_fused<<<PREBLK + edgeBlocks, 256>>>(x, w_ego_u, w_layer_u, n_imp,
                                          edge_src, edge_dst, N, E);

    int Mmain = M & ~3;
    int nDotWarps = (Mmain + CPW - 1) / CPW;
    int nDotBlk = (nDotWarps + 7) / 8;
    if (nDotBlk < 1) nDotBlk = 1;
    k_dot<<<nDotBlk, 256>>>(u_ids, batch_ptr, M);

    k_fin1<<<(M / 4 + 255) / 256, 256>>>(u_ids, batch_ptr, M);

    k_final<<<(M / 4 + 255) / 256, 256>>>(batch_ptr, out, M);
}

// round 16
// speedup vs baseline: 2.1757x; 2.1757x over previous
#include <cuda_runtime.h>
#include <math.h>

#define FDIM 256
#define BMAX 1024
#define MMAX 500000
#define NMAX 200000
#define CPW  32      // candidates per dot-warp (8 iterations x 4)
#define PREBLK 1024  // blocks doing per-node precompute inside k_fused

// Scratch (allocation-free: __device__ globals)
__device__ float    g_groot[BMAX * FDIM];   // per-root x_r * w_ego_root * w_ego_u
__device__ float2   g_rootsc[BMAX];         // {1/max(nr,eps), budgets/200}
__device__ float    g_sv[BMAX];             // x_r . w_layer_v
__device__ unsigned g_pnorm[BMAX];          // encoded float max
__device__ float    g_agg[MMAX];            // segment_sum(sv[edge_src] -> edge_dst)
__device__ float    g_dot[MMAX];            // raw dot(x_u, g_b)
__device__ float    g_pu[MMAX];             // p_u before normalization
__device__ float4   g_node[NMAX];           // {1/max(nu,eps), su, 0.5*n_imp, 0}

__device__ __forceinline__ unsigned f2key(float f) {
    unsigned u = __float_as_uint(f);
    return (u & 0x80000000u) ? ~u : (u | 0x80000000u);
}
__device__ __forceinline__ float key2f(unsigned k) {
    unsigned u = (k & 0x80000000u) ? (k ^ 0x80000000u) : ~k;
    return __uint_as_float(u);
}
__device__ __forceinline__ float dot4(float4 a, float4 b) {
    return a.x * b.x + a.y * b.y + a.z * b.z + a.w * b.w;
}
__device__ __forceinline__ float sq4(float4 a, float4 w) {
    float t0 = a.x * w.x, t1 = a.y * w.y, t2 = a.z * w.z, t3 = a.w * w.w;
    return t0 * t0 + t1 * t1 + t2 * t2 + t3 * t3;
}

// K1: per-root precompute (one block per root) + zero g_agg (strided).
__global__ void k_root(const float* __restrict__ x,
                       const float* __restrict__ w_ego_root,
                       const float* __restrict__ w_ego_u,
                       const float* __restrict__ w_layer_v,
                       const float* __restrict__ budgets,
                       const int*   __restrict__ batch_nodes,
                       int B, int M)
{
    int b = blockIdx.x;
    int f = threadIdx.x;

    for (int j = b * FDIM + f; j < M; j += gridDim.x * FDIM) g_agg[j] = 0.0f;

    float xr = x[(size_t)batch_nodes[b] * FDIM + f];
    float h  = xr * w_ego_root[f];
    g_groot[b * FDIM + f] = h * w_ego_u[f];
    float s1 = h * h;
    float s2 = xr * w_layer_v[f];

    __shared__ float sh1[8], sh2[8];
    #pragma unroll
    for (int o = 16; o; o >>= 1) {
        s1 += __shfl_xor_sync(0xffffffffu, s1, o);
        s2 += __shfl_xor_sync(0xffffffffu, s2, o);
    }
    int w = f >> 5, l = f & 31;
    if (l == 0) { sh1[w] = s1; sh2[w] = s2; }
    __syncthreads();
    if (f == 0) {
        float t1 = 0.f, t2 = 0.f;
        #pragma unroll
        for (int i = 0; i < 8; i++) { t1 += sh1[i]; t2 += sh2[i]; }
        g_rootsc[b] = make_float2(1.0f / fmaxf(sqrtf(t1), 1e-6f),
                                  budgets[b] * (1.0f / 200.0f));
        g_sv[b] = t2;
        g_pnorm[b] = f2key(-INFINITY);
    }
}

// K2: one kernel, three independent block groups running concurrently:
//   [0, nDotBlk)                    candidate dot gather (the long pole)
//   [nDotBlk, nDotBlk+PREBLK)       per-node {invnu, su, n_imp} precompute
//   [nDotBlk+PREBLK, ...)           edge scatter-add
__global__ void __launch_bounds__(256)
k_fused(const float* __restrict__ x,
        const float* __restrict__ w_ego_u,
        const float* __restrict__ w_layer_u,
        const float* __restrict__ n_imp,
        const int* __restrict__ edge_src,
        const int* __restrict__ edge_dst,
        const int* __restrict__ u_ids,
        const int* __restrict__ batch_ptr,
        int N, int E, int M, int nDotBlk)
{
    const float4* x4 = (const float4*)x;

    if (blockIdx.x < nDotBlk) {
        // ---- candidate dots: 8-lanes-per-candidate, 4 cands/warp-iter ----
        int lane  = threadIdx.x & 31;
        int gwarp = blockIdx.x * 8 + (threadIdx.x >> 5);
        int c = lane >> 3;          // candidate slot 0..3
        int s = lane & 7;           // sublane 0..7
        const float4* g4 = (const float4*)g_groot;

        int Mmain = M & ~3;

        // tail: grid-warp 0 handles [Mmain, M) with a 32-lane path
        if (gwarp == 0 && Mmain < M) {
            for (int m = Mmain; m < M; m++) {
                int u = __ldg(u_ids + m);
                int b = __ldg(batch_ptr + m);
                float4 xa = __ldg(x4 + (size_t)u * 64 + lane);
                float4 xb = __ldg(x4 + (size_t)u * 64 + lane + 32);
                float4 ta = __ldg(g4 + (size_t)b * 64 + lane);
                float4 tb = __ldg(g4 + (size_t)b * 64 + lane + 32);
                float d = dot4(xa, ta) + dot4(xb, tb);
                #pragma unroll
                for (int o = 16; o; o >>= 1)
                    d += __shfl_xor_sync(0xffffffffu, d, o);
                if (lane == 0) g_dot[m] = d;
            }
        }

        int base = gwarp * CPW;
        if (base >= Mmain) return;
        int lim = base + CPW; if (lim > Mmain) lim = Mmain;

        for (int m0 = base; m0 < lim; m0 += 4) {
            int4 uu = *(const int4*)(u_ids + m0);
            int4 bb = *(const int4*)(batch_ptr + m0);
            int u = (c == 0) ? uu.x : (c == 1) ? uu.y : (c == 2) ? uu.z : uu.w;
            int b = (c == 0) ? bb.x : (c == 1) ? bb.y : (c == 2) ? bb.z : bb.w;

            const float4* xr = x4 + (size_t)u * 64 + s;
            float4 xv0 = __ldg(xr);
            float4 xv1 = __ldg(xr + 8);
            float4 xv2 = __ldg(xr + 16);
            float4 xv3 = __ldg(xr + 24);
            float4 xv4 = __ldg(xr + 32);
            float4 xv5 = __ldg(xr + 40);
            float4 xv6 = __ldg(xr + 48);
            float4 xv7 = __ldg(xr + 56);

            const float4* gr = g4 + (size_t)b * 64 + s;
            float dot = dot4(xv0, __ldg(gr))
                      + dot4(xv1, __ldg(gr + 8))
                      + dot4(xv2, __ldg(gr + 16))
                      + dot4(xv3, __ldg(gr + 24))
                      + dot4(xv4, __ldg(gr + 32))
                      + dot4(xv5, __ldg(gr + 40))
                      + dot4(xv6, __ldg(gr + 48))
                      + dot4(xv7, __ldg(gr + 56));

            #pragma unroll
            for (int o = 4; o; o >>= 1)
                dot += __shfl_xor_sync(0xffffffffu, dot, o);

            if (s == 0) g_dot[m0 + c] = dot;   // 4 lanes, 16B coalesced
        }
    } else if (blockIdx.x < nDotBlk + PREBLK) {
        // ---- per-node precompute: {invnu, su, 0.5*n_imp} ----
        int lane = threadIdx.x & 31;
        int gw = (blockIdx.x - nDotBlk) * 8 + (threadIdx.x >> 5);
        int nw = PREBLK * 8;

        float4 wea = __ldg(((const float4*)w_ego_u)   + lane);
        float4 web = __ldg(((const float4*)w_ego_u)   + lane + 32);
        float4 wla = __ldg(((const float4*)w_layer_u) + lane);
        float4 wlb = __ldg(((const float4*)w_layer_u) + lane + 32);

        for (int n = gw * 2; n < N; n += nw * 2) {
            bool two = (n + 1 < N);
            float4 a0 = __ldg(x4 + (size_t)n * 64 + lane);
            float4 b0 = __ldg(x4 + (size_t)n * 64 + lane + 32);
            int n1 = two ? n + 1 : n;
            float4 a1 = __ldg(x4 + (size_t)n1 * 64 + lane);
            float4 b1 = __ldg(x4 + (size_t)n1 * 64 + lane + 32);

            float nu0 = sq4(a0, wea) + sq4(b0, web);
            float su0 = dot4(a0, wla) + dot4(b0, wlb);
            float nu1 = sq4(a1, wea) + sq4(b1, web);
            float su1 = dot4(a1, wla) + dot4(b1, wlb);

            nu0 += __shfl_xor_sync(0xffffffffu, nu0, 16);
            su0 += __shfl_xor_sync(0xffffffffu, su0, 16);
            nu1 += __shfl_xor_sync(0xffffffffu, nu1, 16);
            su1 += __shfl_xor_sync(0xffffffffu, su1, 16);
            bool hi16 = (lane & 16) != 0;
            float v0 = hi16 ? su0 : nu0;      // lanes<16: nu, >=16: su
            float v1 = hi16 ? su1 : nu1;
            #pragma unroll
            for (int o = 8; o; o >>= 1) {
                v0 += __shfl_xor_sync(0xffffffffu, v0, o);
                v1 += __shfl_xor_sync(0xffffffffu, v1, o);
            }
            float su0f = __shfl_sync(0xffffffffu, v0, 16);
            float su1f = __shfl_sync(0xffffffffu, v1, 16);
            if (lane == 0) {
                g_node[n] = make_float4(1.0f / fmaxf(sqrtf(v0), 1e-6f), su0f,
                                        0.5f * __ldg(n_imp + n), 0.0f);
                if (two)
                    g_node[n1] = make_float4(1.0f / fmaxf(sqrtf(v1), 1e-6f), su1f,
                                             0.5f * __ldg(n_imp + n1), 0.0f);
            }
        }
    } else {
        // ---- edge scatter-add: 4 edges per thread ----
        int i = ((blockIdx.x - nDotBlk - PREBLK) * (int)blockDim.x
                 + (int)threadIdx.x) * 4;
        if (i + 3 < E) {
            int4 s = *(const int4*)(edge_src + i);
            int4 d = *(const int4*)(edge_dst + i);
            atomicAdd(&g_agg[d.x], g_sv[s.x]);
            atomicAdd(&g_agg[d.y], g_sv[s.y]);
            atomicAdd(&g_agg[d.z], g_sv[s.z]);
            atomicAdd(&g_agg[d.w], g_sv[s.w]);
        } else {
            for (int j = i; j < E; j++)
                atomicAdd(&g_agg[edge_dst[j]], g_sv[edge_src[j]]);
        }
    }
}

// K3: finalize — p_u from dot/agg/node tables + per-batch max (warp-merged).
__global__ void __launch_bounds__(256)
k_fin1(const int* __restrict__ u_ids,
       const int* __restrict__ batch_ptr, int M)
{
    int idx = blockIdx.x * blockDim.x + threadIdx.x;
    int m = idx * 4;
    bool full = (m + 3 < M);
    unsigned act = __ballot_sync(0xffffffffu, full);

    if (full) {
        int4   uu = *(const int4*)(u_ids + m);
        int4   bb = *(const int4*)(batch_ptr + m);
        float4 dt = *(const float4*)(g_dot + m);
        float4 ag = *(const float4*)(g_agg + m);

        float4 nd0 = __ldg((const float4*)g_node + uu.x);
        float4 nd1 = __ldg((const float4*)g_node + uu.y);
        float4 nd2 = __ldg((const float4*)g_node + uu.z);
        float4 nd3 = __ldg((const float4*)g_node + uu.w);
        float2 rs0 = __ldg(g_rootsc + bb.x);
        float2 rs1 = __ldg(g_rootsc + bb.y);
        float2 rs2 = __ldg(g_rootsc + bb.z);
        float2 rs3 = __ldg(g_rootsc + bb.w);

        float4 r;
        r.x = (dt.x * rs0.x * nd0.x + tanhf(ag.x + nd0.y)) * nd0.z * rs0.y;
        r.y = (dt.y * rs1.x * nd1.x + tanhf(ag.y + nd1.y)) * nd1.z * rs1.y;
        r.z = (dt.z * rs2.x * nd2.x + tanhf(ag.z + nd2.y)) * nd2.z * rs2.y;
        r.w = (dt.w * rs3.x * nd3.x + tanhf(ag.w + nd3.y)) * nd3.z * rs3.y;
        *(float4*)(g_pu + m) = r;

        unsigned kx = f2key(r.x), ky = f2key(r.y);
        unsigned kz = f2key(r.z), kw = f2key(r.w);
        bool uni4 = (bb.x == bb.w);
        unsigned kmax = kx > ky ? kx : ky;
        kmax = kmax > kz ? kmax : kz;
        kmax = kmax > kw ? kmax : kw;

        if (act == 0xffffffffu) {     // whole warp in this path: safe to shfl
            unsigned bFirst = __shfl_sync(0xffffffffu, (unsigned)bb.x, 0);
            bool warpUni = __all_sync(0xffffffffu,
                                      uni4 && (unsigned)bb.x == bFirst);
            if (warpUni) {
                #pragma unroll
                for (int o = 16; o; o >>= 1) {
                    unsigned t = __shfl_xor_sync(0xffffffffu, kmax, o);
                    kmax = kmax > t ? kmax : t;
                }
                if ((threadIdx.x & 31) == 0) atomicMax(&g_pnorm[bb.x], kmax);
                return;
            }
        }
        if (uni4) {
            atomicMax(&g_pnorm[bb.x], kmax);
        } else {
            atomicMax(&g_pnorm[bb.x], kx);
            atomicMax(&g_pnorm[bb.y], ky);
            atomicMax(&g_pnorm[bb.z], kz);
            atomicMax(&g_pnorm[bb.w], kw);
        }
    } else {
        for (int j = m; j < M; j++) {
            int u = __ldg(u_ids + j);
            int b = __ldg(batch_ptr + j);
            float4 nd = __ldg((const float4*)g_node + u);
            float2 rs = __ldg(g_rootsc + b);
            float p = (g_dot[j] * rs.x * nd.x + tanhf(g_agg[j] + nd.y))
                      * nd.z * rs.y;
            g_pu[j] = p;
            atomicMax(&g_pnorm[b], f2key(p));
        }
    }
}

// K5: normalize + nan/inf replace + clip (vectorized)
__global__ void k_final(const int* __restrict__ batch_ptr,
                        float* __restrict__ out, int M)
{
    int m = (blockIdx.x * blockDim.x + threadIdx.x) * 4;
    if (m + 3 < M) {
        int4   bp = *(const int4*)(batch_ptr + m);
        float4 pu = *(const float4*)(g_pu + m);
        float4 r;
        {
            float p = pu.x / key2f(g_pnorm[bp.x]) + 1.0f;
            if (isnan(p)) p = 0.0f; else if (isinf(p)) p = 1.0f;
            r.x = fminf(fmaxf(p, 1e-5f), 1.0f);
        }
        {
            float p = pu.y / key2f(g_pnorm[bp.y]) + 1.0f;
            if (isnan(p)) p = 0.0f; else if (isinf(p)) p = 1.0f;
            r.y = fminf(fmaxf(p, 1e-5f), 1.0f);
        }
        {
            float p = pu.z / key2f(g_pnorm[bp.z]) + 1.0f;
            if (isnan(p)) p = 0.0f; else if (isinf(p)) p = 1.0f;
            r.z = fminf(fmaxf(p, 1e-5f), 1.0f);
        }
        {
            float p = pu.w / key2f(g_pnorm[bp.w]) + 1.0f;
            if (isnan(p)) p = 0.0f; else if (isinf(p)) p = 1.0f;
            r.w = fminf(fmaxf(p, 1e-5f), 1.0f);
        }
        *(float4*)(out + m) = r;
    } else {
        for (int j = m; j < M; j++) {
            float p = g_pu[j] / key2f(g_pnorm[batch_ptr[j]]) + 1.0f;
            if (isnan(p)) p = 0.0f; else if (isinf(p)) p = 1.0f;
            out[j] = fminf(fmaxf(p, 1e-5f), 1.0f);
        }
    }
}

extern "C" void kernel_launch(void* const* d_in, const int* in_sizes, int n_in,
                              void* d_out, int out_size)
{
    const float* x           = (const float*)d_in[0];
    const float* w_ego_root  = (const float*)d_in[1];
    const float* w_ego_u     = (const float*)d_in[2];
    const float* w_layer_v   = (const float*)d_in[3];
    const float* w_layer_u   = (const float*)d_in[4];
    const float* n_imp       = (const float*)d_in[5];
    const float* budgets     = (const float*)d_in[6];
    const int*   batch_nodes = (const int*)d_in[7];
    const int*   u_ids       = (const int*)d_in[8];
    const int*   batch_ptr   = (const int*)d_in[9];
    const int*   edge_src    = (const int*)d_in[10];
    const int*   edge_dst    = (const int*)d_in[11];
    float* out = (float*)d_out;

    int B = in_sizes[7];
    int M = in_sizes[8];
    int E = in_sizes[10];
    int N = in_sizes[0] / FDIM;

    k_root<<<B, FDIM>>>(x, w_ego_root, w_ego_u, w_layer_v, budgets,
                        batch_nodes, B, M);

    int Mmain = M & ~3;
    int nDotWarps = (Mmain + CPW - 1) / CPW;
    int nDotBlk = (nDotWarps + 7) / 8;
    if (nDotBlk < 1) nDotBlk = 1;
    int edgeBlocks = (E / 4 + 255) / 256;
    k_fused<<<nDotBlk + PREBLK + edgeBlocks, 256>>>(
        x, w_ego_u, w_layer_u, n_imp, edge_src, edge_dst,
        u_ids, batch_ptr, N, E, M, nDotBlk);

    k_fin1<<<(M / 4 + 255) / 256, 256>>>(u_ids, batch_ptr, M);

    k_final<<<(M / 4 + 255) / 256, 256>>>(batch_ptr, out, M);
}

// round 17
// speedup vs baseline: 2.2058x; 1.0138x over previous
#include <cuda_runtime.h>
#include <math.h>

#define FDIM 256
#define BMAX 1024
#define MMAX 500000
#define NMAX 200000
#define CPW  32      // candidates per dot-warp (8 iterations x 4)
#define PREBLK 1024  // blocks doing per-node precompute inside k_fused

// Scratch (allocation-free: __device__ globals)
__device__ float    g_groot[BMAX * FDIM];   // per-root x_r * w_ego_root * w_ego_u
__device__ float2   g_rootsc[BMAX];         // {1/max(nr,eps), budgets/200}
__device__ float    g_sv[BMAX];             // x_r . w_layer_v
__device__ unsigned g_pnorm[BMAX];          // encoded float max
__device__ float    g_agg[MMAX];            // segment_sum(sv[edge_src] -> edge_dst)
__device__ float    g_dot[MMAX];            // raw dot(x_u, g_b)
__device__ float4   g_node[NMAX];           // {1/max(nu,eps), su, 0.5*n_imp, 0}
__device__ unsigned g_barrier;              // arrival counter for k_fin grid barrier

__device__ __forceinline__ unsigned f2key(float f) {
    unsigned u = __float_as_uint(f);
    return (u & 0x80000000u) ? ~u : (u | 0x80000000u);
}
__device__ __forceinline__ float key2f(unsigned k) {
    unsigned u = (k & 0x80000000u) ? (k ^ 0x80000000u) : ~k;
    return __uint_as_float(u);
}
__device__ __forceinline__ float dot4(float4 a, float4 b) {
    return a.x * b.x + a.y * b.y + a.z * b.z + a.w * b.w;
}
__device__ __forceinline__ float sq4(float4 a, float4 w) {
    float t0 = a.x * w.x, t1 = a.y * w.y, t2 = a.z * w.z, t3 = a.w * w.w;
    return t0 * t0 + t1 * t1 + t2 * t2 + t3 * t3;
}
__device__ __forceinline__ unsigned ldcg_u32(const unsigned* p) {
    unsigned v;
    asm volatile("ld.global.cg.u32 %0, [%1];" : "=r"(v) : "l"(p));
    return v;
}

// K1: per-root precompute (one block per root) + zero g_agg (strided).
__global__ void k_root(const float* __restrict__ x,
                       const float* __restrict__ w_ego_root,
                       const float* __restrict__ w_ego_u,
                       const float* __restrict__ w_layer_v,
                       const float* __restrict__ budgets,
                       const int*   __restrict__ batch_nodes,
                       int B, int M)
{
    int b = blockIdx.x;
    int f = threadIdx.x;

    if (b == 0 && f == 0) g_barrier = 0;    // reset grid-barrier each replay

    for (int j = b * FDIM + f; j < M; j += gridDim.x * FDIM) g_agg[j] = 0.0f;

    float xr = x[(size_t)batch_nodes[b] * FDIM + f];
    float h  = xr * w_ego_root[f];
    g_groot[b * FDIM + f] = h * w_ego_u[f];
    float s1 = h * h;
    float s2 = xr * w_layer_v[f];

    __shared__ float sh1[8], sh2[8];
    #pragma unroll
    for (int o = 16; o; o >>= 1) {
        s1 += __shfl_xor_sync(0xffffffffu, s1, o);
        s2 += __shfl_xor_sync(0xffffffffu, s2, o);
    }
    int w = f >> 5, l = f & 31;
    if (l == 0) { sh1[w] = s1; sh2[w] = s2; }
    __syncthreads();
    if (f == 0) {
        float t1 = 0.f, t2 = 0.f;
        #pragma unroll
        for (int i = 0; i < 8; i++) { t1 += sh1[i]; t2 += sh2[i]; }
        g_rootsc[b] = make_float2(1.0f / fmaxf(sqrtf(t1), 1e-6f),
                                  budgets[b] * (1.0f / 200.0f));
        g_sv[b] = t2;
        g_pnorm[b] = f2key(-INFINITY);
    }
}

// K2: one kernel, three independent block groups running concurrently:
//   [0, nDotBlk)                    candidate dot gather (the long pole)
//   [nDotBlk, nDotBlk+PREBLK)       per-node {invnu, su, n_imp} precompute
//   [nDotBlk+PREBLK, ...)           edge scatter-add
__global__ void __launch_bounds__(256)
k_fused(const float* __restrict__ x,
        const float* __restrict__ w_ego_u,
        const float* __restrict__ w_layer_u,
        const float* __restrict__ n_imp,
        const int* __restrict__ edge_src,
        const int* __restrict__ edge_dst,
        const int* __restrict__ u_ids,
        const int* __restrict__ batch_ptr,
        int N, int E, int M, int nDotBlk)
{
    const float4* x4 = (const float4*)x;

    if (blockIdx.x < nDotBlk) {
        // ---- candidate dots: 8-lanes-per-candidate, 4 cands/warp-iter ----
        int lane  = threadIdx.x & 31;
        int gwarp = blockIdx.x * 8 + (threadIdx.x >> 5);
        int c = lane >> 3;          // candidate slot 0..3
        int s = lane & 7;           // sublane 0..7
        const float4* g4 = (const float4*)g_groot;

        int Mmain = M & ~3;

        // tail: grid-warp 0 handles [Mmain, M) with a 32-lane path
        if (gwarp == 0 && Mmain < M) {
            for (int m = Mmain; m < M; m++) {
                int u = __ldg(u_ids + m);
                int b = __ldg(batch_ptr + m);
                float4 xa = __ldg(x4 + (size_t)u * 64 + lane);
                float4 xb = __ldg(x4 + (size_t)u * 64 + lane + 32);
                float4 ta = __ldg(g4 + (size_t)b * 64 + lane);
                float4 tb = __ldg(g4 + (size_t)b * 64 + lane + 32);
                float d = dot4(xa, ta) + dot4(xb, tb);
                #pragma unroll
                for (int o = 16; o; o >>= 1)
                    d += __shfl_xor_sync(0xffffffffu, d, o);
                if (lane == 0) g_dot[m] = d;
            }
        }

        int base = gwarp * CPW;
        if (base >= Mmain) return;
        int lim = base + CPW; if (lim > Mmain) lim = Mmain;

        for (int m0 = base; m0 < lim; m0 += 4) {
            int4 uu = *(const int4*)(u_ids + m0);
            int4 bb = *(const int4*)(batch_ptr + m0);
            int u = (c == 0) ? uu.x : (c == 1) ? uu.y : (c == 2) ? uu.z : uu.w;
            int b = (c == 0) ? bb.x : (c == 1) ? bb.y : (c == 2) ? bb.z : bb.w;

            const float4* xr = x4 + (size_t)u * 64 + s;
            float4 xv0 = __ldg(xr);
            float4 xv1 = __ldg(xr + 8);
            float4 xv2 = __ldg(xr + 16);
            float4 xv3 = __ldg(xr + 24);
            float4 xv4 = __ldg(xr + 32);
            float4 xv5 = __ldg(xr + 40);
            float4 xv6 = __ldg(xr + 48);
            float4 xv7 = __ldg(xr + 56);

            const float4* gr = g4 + (size_t)b * 64 + s;
            float dot = dot4(xv0, __ldg(gr))
                      + dot4(xv1, __ldg(gr + 8))
                      + dot4(xv2, __ldg(gr + 16))
                      + dot4(xv3, __ldg(gr + 24))
                      + dot4(xv4, __ldg(gr + 32))
                      + dot4(xv5, __ldg(gr + 40))
                      + dot4(xv6, __ldg(gr + 48))
                      + dot4(xv7, __ldg(gr + 56));

            #pragma unroll
            for (int o = 4; o; o >>= 1)
                dot += __shfl_xor_sync(0xffffffffu, dot, o);

            if (s == 0) g_dot[m0 + c] = dot;   // 4 lanes, 16B coalesced
        }
    } else if (blockIdx.x < nDotBlk + PREBLK) {
        // ---- per-node precompute: {invnu, su, 0.5*n_imp} ----
        int lane = threadIdx.x & 31;
        int gw = (blockIdx.x - nDotBlk) * 8 + (threadIdx.x >> 5);
        int nw = PREBLK * 8;

        float4 wea = __ldg(((const float4*)w_ego_u)   + lane);
        float4 web = __ldg(((const float4*)w_ego_u)   + lane + 32);
        float4 wla = __ldg(((const float4*)w_layer_u) + lane);
        float4 wlb = __ldg(((const float4*)w_layer_u) + lane + 32);

        for (int n = gw * 2; n < N; n += nw * 2) {
            bool two = (n + 1 < N);
            float4 a0 = __ldg(x4 + (size_t)n * 64 + lane);
            float4 b0 = __ldg(x4 + (size_t)n * 64 + lane + 32);
            int n1 = two ? n + 1 : n;
            float4 a1 = __ldg(x4 + (size_t)n1 * 64 + lane);
            float4 b1 = __ldg(x4 + (size_t)n1 * 64 + lane + 32);

            float nu0 = sq4(a0, wea) + sq4(b0, web);
            float su0 = dot4(a0, wla) + dot4(b0, wlb);
            float nu1 = sq4(a1, wea) + sq4(b1, web);
            float su1 = dot4(a1, wla) + dot4(b1, wlb);

            nu0 += __shfl_xor_sync(0xffffffffu, nu0, 16);
            su0 += __shfl_xor_sync(0xffffffffu, su0, 16);
            nu1 += __shfl_xor_sync(0xffffffffu, nu1, 16);
            su1 += __shfl_xor_sync(0xffffffffu, su1, 16);
            bool hi16 = (lane & 16) != 0;
            float v0 = hi16 ? su0 : nu0;      // lanes<16: nu, >=16: su
            float v1 = hi16 ? su1 : nu1;
            #pragma unroll
            for (int o = 8; o; o >>= 1) {
                v0 += __shfl_xor_sync(0xffffffffu, v0, o);
                v1 += __shfl_xor_sync(0xffffffffu, v1, o);
            }
            float su0f = __shfl_sync(0xffffffffu, v0, 16);
            float su1f = __shfl_sync(0xffffffffu, v1, 16);
            if (lane == 0) {
                g_node[n] = make_float4(1.0f / fmaxf(sqrtf(v0), 1e-6f), su0f,
                                        0.5f * __ldg(n_imp + n), 0.0f);
                if (two)
                    g_node[n1] = make_float4(1.0f / fmaxf(sqrtf(v1), 1e-6f), su1f,
                                             0.5f * __ldg(n_imp + n1), 0.0f);
            }
        }
    } else {
        // ---- edge scatter-add: 4 edges per thread ----
        int i = ((blockIdx.x - nDotBlk - PREBLK) * (int)blockDim.x
                 + (int)threadIdx.x) * 4;
        if (i + 3 < E) {
            int4 s = *(const int4*)(edge_src + i);
            int4 d = *(const int4*)(edge_dst + i);
            atomicAdd(&g_agg[d.x], g_sv[s.x]);
            atomicAdd(&g_agg[d.y], g_sv[s.y]);
            atomicAdd(&g_agg[d.z], g_sv[s.z]);
            atomicAdd(&g_agg[d.w], g_sv[s.w]);
        } else {
            for (int j = i; j < E; j++)
                atomicAdd(&g_agg[edge_dst[j]], g_sv[edge_src[j]]);
        }
    }
}

// K3: merged finalize + normalize. Phase 1: compute p, atomicMax per batch.
// Grid barrier (all 489 blocks co-resident). Phase 2: normalize from
// registers (no g_pu round-trip), write out.
__global__ void __launch_bounds__(256)
k_fin(const int* __restrict__ u_ids,
      const int* __restrict__ batch_ptr,
      float* __restrict__ out, int M)
{
    int idx = blockIdx.x * blockDim.x + threadIdx.x;
    int m = idx * 4;
    bool full = (m + 3 < M);
    unsigned act = __ballot_sync(0xffffffffu, full);

    float pv0 = 0.f, pv1 = 0.f, pv2 = 0.f, pv3 = 0.f;
    int4 bb = make_int4(0, 0, 0, 0);
    int cnt = 0;

    if (full) {
        cnt = 4;
        int4   uu = *(const int4*)(u_ids + m);
        bb = *(const int4*)(batch_ptr + m);
        float4 dt = *(const float4*)(g_dot + m);
        float4 ag = *(const float4*)(g_agg + m);

        float4 nd0 = __ldg((const float4*)g_node + uu.x);
        float4 nd1 = __ldg((const float4*)g_node + uu.y);
        float4 nd2 = __ldg((const float4*)g_node + uu.z);
        float4 nd3 = __ldg((const float4*)g_node + uu.w);
        float2 rs0 = __ldg(g_rootsc + bb.x);
        float2 rs1 = __ldg(g_rootsc + bb.y);
        float2 rs2 = __ldg(g_rootsc + bb.z);
        float2 rs3 = __ldg(g_rootsc + bb.w);

        pv0 = (dt.x * rs0.x * nd0.x + tanhf(ag.x + nd0.y)) * nd0.z * rs0.y;
        pv1 = (dt.y * rs1.x * nd1.x + tanhf(ag.y + nd1.y)) * nd1.z * rs1.y;
        pv2 = (dt.z * rs2.x * nd2.x + tanhf(ag.z + nd2.y)) * nd2.z * rs2.y;
        pv3 = (dt.w * rs3.x * nd3.x + tanhf(ag.w + nd3.y)) * nd3.z * rs3.y;

        unsigned kx = f2key(pv0), ky = f2key(pv1);
        unsigned kz = f2key(pv2), kw = f2key(pv3);
        bool uni4 = (bb.x == bb.w);
        unsigned kmax = kx > ky ? kx : ky;
        kmax = kmax > kz ? kmax : kz;
        kmax = kmax > kw ? kmax : kw;

        bool done = false;
        if (act == 0xffffffffu) {     // whole warp full: safe to shfl
            unsigned bFirst = __shfl_sync(0xffffffffu, (unsigned)bb.x, 0);
            bool warpUni = __all_sync(0xffffffffu,
                                      uni4 && (unsigned)bb.x == bFirst);
            if (warpUni) {
                unsigned km = kmax;
                #pragma unroll
                for (int o = 16; o; o >>= 1) {
                    unsigned t = __shfl_xor_sync(0xffffffffu, km, o);
                    km = km > t ? km : t;
                }
                if ((threadIdx.x & 31) == 0) atomicMax(&g_pnorm[bb.x], km);
                done = true;
            }
        }
        if (!done) {
            if (uni4) {
                atomicMax(&g_pnorm[bb.x], kmax);
            } else {
                atomicMax(&g_pnorm[bb.x], kx);
                atomicMax(&g_pnorm[bb.y], ky);
                atomicMax(&g_pnorm[bb.z], kz);
                atomicMax(&g_pnorm[bb.w], kw);
            }
        }
    } else if (m < M) {
        cnt = M - m;                 // 1..3
        float pvs[3]; int bvs[3];
        for (int i = 0; i < cnt; i++) {
            int j = m + i;
            int u = __ldg(u_ids + j);
            int b = __ldg(batch_ptr + j);
            float4 nd = __ldg((const float4*)g_node + u);
            float2 rs = __ldg(g_rootsc + b);
            float p = (g_dot[j] * rs.x * nd.x + tanhf(g_agg[j] + nd.y))
                      * nd.z * rs.y;
            pvs[i] = p; bvs[i] = b;
            atomicMax(&g_pnorm[b], f2key(p));
        }
        pv0 = pvs[0];
        pv1 = (cnt > 1) ? pvs[1] : 0.f;
        pv2 = (cnt > 2) ? pvs[2] : 0.f;
        bb.x = bvs[0];
        bb.y = (cnt > 1) ? bvs[1] : bvs[0];
        bb.z = (cnt > 2) ? bvs[2] : bvs[0];
    }

    // ---- grid barrier: all blocks co-resident (489 < min occupancy cap) ----
    __threadfence();
    __syncthreads();
    if (threadIdx.x == 0) {
        atomicAdd(&g_barrier, 1u);
        while (ldcg_u32(&g_barrier) < gridDim.x) { __nanosleep(200); }
    }
    __syncthreads();
    __threadfence();

    // ---- phase 2: normalize from registers, write out ----
    if (full) {
        float n0 = key2f(ldcg_u32(&g_pnorm[bb.x]));
        float n1 = key2f(ldcg_u32(&g_pnorm[bb.y]));
        float n2 = key2f(ldcg_u32(&g_pnorm[bb.z]));
        float n3 = key2f(ldcg_u32(&g_pnorm[bb.w]));
        float4 r;
        {
            float p = pv0 / n0 + 1.0f;
            if (isnan(p)) p = 0.0f; else if (isinf(p)) p = 1.0f;
            r.x = fminf(fmaxf(p, 1e-5f), 1.0f);
        }
        {
            float p = pv1 / n1 + 1.0f;
            if (isnan(p)) p = 0.0f; else if (isinf(p)) p = 1.0f;
            r.y = fminf(fmaxf(p, 1e-5f), 1.0f);
        }
        {
            float p = pv2 / n2 + 1.0f;
            if (isnan(p)) p = 0.0f; else if (isinf(p)) p = 1.0f;
            r.z = fminf(fmaxf(p, 1e-5f), 1.0f);
        }
        {
            float p = pv3 / n3 + 1.0f;
            if (isnan(p)) p = 0.0f; else if (isinf(p)) p = 1.0f;
            r.w = fminf(fmaxf(p, 1e-5f), 1.0f);
        }
        *(float4*)(out + m) = r;
    } else if (m < M) {
        float pvs[3] = {pv0, pv1, pv2};
        int   bvs[3] = {bb.x, bb.y, bb.z};
        for (int i = 0; i < cnt; i++) {
            float p = pvs[i] / key2f(ldcg_u32(&g_pnorm[bvs[i]])) + 1.0f;
            if (isnan(p)) p = 0.0f; else if (isinf(p)) p = 1.0f;
            out[m + i] = fminf(fmaxf(p, 1e-5f), 1.0f);
        }
    }
}

extern "C" void kernel_launch(void* const* d_in, const int* in_sizes, int n_in,
                              void* d_out, int out_size)
{
    const float* x           = (const float*)d_in[0];
    const float* w_ego_root  = (const float*)d_in[1];
    const float* w_ego_u     = (const float*)d_in[2];
    const float* w_layer_v   = (const float*)d_in[3];
    const float* w_layer_u   = (const float*)d_in[4];
    const float* n_imp       = (const float*)d_in[5];
    const float* budgets     = (const float*)d_in[6];
    const int*   batch_nodes = (const int*)d_in[7];
    const int*   u_ids       = (const int*)d_in[8];
    const int*   batch_ptr   = (const int*)d_in[9];
    const int*   edge_src    = (const int*)d_in[10];
    const int*   edge_dst    = (const int*)d_in[11];
    float* out = (float*)d_out;

    int B = in_sizes[7];
    int M = in_sizes[8];
    int E = in_sizes[10];
    int N = in_sizes[0] / FDIM;

    k_root<<<B, FDIM>>>(x, w_ego_root, w_ego_u, w_layer_v, budgets,
                        batch_nodes, B, M);

    int Mmain = M & ~3;
    int nDotWarps = (Mmain + CPW - 1) / CPW;
    int nDotBlk = (nDotWarps + 7) / 8;
    if (nDotBlk < 1) nDotBlk = 1;
    int edgeBlocks = (E / 4 + 255) / 256;
    k_fused<<<nDotBlk + PREBLK + edgeBlocks, 256>>>(
        x, w_ego_u, w_layer_u, n_imp, edge_src, edge_dst,
        u_ids, batch_ptr, N, E, M, nDotBlk);

    k_fin<<<(M / 4 + 255) / 256, 256>>>(u_ids, batch_ptr, out, M);
}